// round 15
// baseline (speedup 1.0000x reference)
#include <cuda_runtime.h>
#include <math.h>

#define NB    1024
#define SIN   256
#define SPR   128
#define HIDN  512

// 1/sqrt(3) * log2(e): fold scores into exp2 domain
#define C_SCALE 0.83294064f
// log2(e): additive causal "mask" of +1.0 in exp2 domain
#define L2E 1.4426950408889634f

typedef unsigned long long u64;

struct Params {
    const float* X;           const float* T;
    const float* enc_in_w;    const float* enc_in_b;
    const float* enc_out_w;   const float* enc_out_b;
    const float* enc_ln1_w;   const float* enc_ln1_b;
    const float* enc_lin1_w;  const float* enc_lin1_b;
    const float* enc_lin2_w;  const float* enc_lin2_b;
    const float* enc_ln2_w;   const float* enc_ln2_b;
    const float* dec_a1_in_w; const float* dec_a1_in_b;
    const float* dec_a1_out_w;const float* dec_a1_out_b;
    const float* dec_ln1_w;   const float* dec_ln1_b;
    const float* dec_a2_in_w; const float* dec_a2_in_b;
    const float* dec_a2_out_w;const float* dec_a2_out_b;
    const float* dec_lin1_w;  const float* dec_lin1_b;
    const float* dec_lin2_w;  const float* dec_lin2_b;
    const float* dec_ln3_w;   const float* dec_ln3_b;
    float* out;
};

// ---- batch-invariant precomputed state (written by prep kernel) ----
__device__ float4 g_pos[SIN];          // pos_enc rows as float4
__device__ float  g_mats[72];          // 6 x (3x3 mat + 3 bias):
                                       // [0)MqE [12)VoE [24)MqD1 [36)VoD1 [48)MqD2 [60)VoD2
__device__ float4 g_wff_enc[HIDN * 2]; // packed enc FFN weights
__device__ float4 g_wff_dec[HIDN * 2]; // packed dec FFN weights

__device__ __forceinline__ float ex2f(float x) {
    float y; asm("ex2.approx.ftz.f32 %0, %1;" : "=f"(y) : "f"(x)); return y;
}
__device__ __forceinline__ float rcpf(float x) {
    float y; asm("rcp.approx.ftz.f32 %0, %1;" : "=f"(y) : "f"(x)); return y;
}

// ---- packed f32x2 ops (Blackwell) ----
__device__ __forceinline__ u64 fma2(u64 a, u64 b, u64 c) {
    u64 d; asm("fma.rn.f32x2 %0, %1, %2, %3;" : "=l"(d) : "l"(a), "l"(b), "l"(c)); return d;
}
__device__ __forceinline__ u64 mul2(u64 a, u64 b) {
    u64 d; asm("mul.rn.f32x2 %0, %1, %2;" : "=l"(d) : "l"(a), "l"(b)); return d;
}
__device__ __forceinline__ u64 add2(u64 a, u64 b) {
    u64 d; asm("add.rn.f32x2 %0, %1, %2;" : "=l"(d) : "l"(a), "l"(b)); return d;
}
__device__ __forceinline__ u64 pack2(float lo, float hi) {
    u64 d; asm("mov.b64 %0, {%1, %2};" : "=l"(d) : "f"(lo), "f"(hi)); return d;
}
__device__ __forceinline__ void unpack2(u64 d, float& a, float& b) {
    asm("mov.b64 {%0, %1}, %2;" : "=f"(a), "=f"(b) : "l"(d));
}
__device__ __forceinline__ float hadd2(u64 d) {
    float a, b; unpack2(d, a, b); return a + b;
}

// Key-pair attention step: lanes = 2 keys vs 1 broadcast query.
__device__ __forceinline__ void qstep(u64 q0p, u64 q1p, u64 q2p,
                                      u64 xp, u64 yp, u64 zp,
                                      u64& aX, u64& aY, u64& aZ, u64& aL) {
    u64 d = fma2(q2p, zp, fma2(q1p, yp, mul2(q0p, xp)));
    float s0, s1; unpack2(d, s0, s1);
    u64 pp = pack2(ex2f(s0), ex2f(s1));
    aX = fma2(pp, xp, aX);
    aY = fma2(pp, yp, aY);
    aZ = fma2(pp, zp, aZ);
    aL = add2(aL, pp);
}
__device__ __forceinline__ void hsum4(u64 aX, u64 aY, u64 aZ, u64 aL,
                                      float& x, float& y, float& z, float& l) {
    x = hadd2(aX); y = hadd2(aY); z = hadd2(aZ); l = hadd2(aL);
}

// Query-pair step: lanes = (queryA, queryB), key broadcast in both lanes.
__device__ __forceinline__ void qpair_step(u64 qp0, u64 qp1, u64 qp2,
                                           float kx, float ky, float kz,
                                           u64& aX, u64& aY, u64& aZ, u64& aL) {
    u64 kxp = pack2(kx, kx), kyp = pack2(ky, ky), kzp = pack2(kz, kz);
    u64 d = fma2(qp2, kzp, fma2(qp1, kyp, mul2(qp0, kxp)));
    float sA, sB; unpack2(d, sA, sB);
    u64 pp = pack2(ex2f(sA), ex2f(sB));
    aX = fma2(pp, kxp, aX);
    aY = fma2(pp, kyp, aY);
    aZ = fma2(pp, kzp, aZ);
    aL = add2(aL, pp);
}
// Masked: reference ADDS tril(ones) -> +log2(e) in exp2 domain, per lane.
__device__ __forceinline__ void qpair_step_m(u64 qp0, u64 qp1, u64 qp2,
                                             float kx, float ky, float kz,
                                             int j, int rowA, int rowB,
                                             u64& aX, u64& aY, u64& aZ, u64& aL) {
    u64 kxp = pack2(kx, kx), kyp = pack2(ky, ky), kzp = pack2(kz, kz);
    u64 d = fma2(qp2, kzp, fma2(qp1, kyp, mul2(qp0, kxp)));
    float sA, sB; unpack2(d, sA, sB);
    sA += (j <= rowA) ? L2E : 0.f;
    sB += (j <= rowB) ? L2E : 0.f;
    u64 pp = pack2(ex2f(sA), ex2f(sB));
    aX = fma2(pp, kxp, aX);
    aY = fma2(pp, kyp, aY);
    aZ = fma2(pp, kzp, aZ);
    aL = add2(aL, pp);
}

// Fused two-value block reduction (2 barriers). (Proven R12 form.)
__device__ __forceinline__ void block_sum2(float& a, float& b, float* red) {
    #pragma unroll
    for (int o = 16; o; o >>= 1) {
        a += __shfl_xor_sync(0xffffffffu, a, o);
        b += __shfl_xor_sync(0xffffffffu, b, o);
    }
    int w = threadIdx.x >> 5;
    if ((threadIdx.x & 31) == 0) { red[w] = a; red[8 + w] = b; }
    __syncthreads();
    if (threadIdx.x < 16) {
        float x = red[threadIdx.x];
        x += __shfl_xor_sync(0x0000ffffu, x, 4);
        x += __shfl_xor_sync(0x0000ffffu, x, 2);
        x += __shfl_xor_sync(0x0000ffffu, x, 1);
        if ((threadIdx.x & 7) == 0) red[16 + (threadIdx.x >> 3)] = x;
    }
    __syncthreads();
    a = red[16]; b = red[17];
}

__device__ __forceinline__ void proj3(const float* w, const float* bias,
                                      float x0, float x1, float x2,
                                      float& o0, float& o1, float& o2) {
    o0 = fmaf(w[0], x0, fmaf(w[1], x1, fmaf(w[2], x2, bias[0])));
    o1 = fmaf(w[3], x0, fmaf(w[4], x1, fmaf(w[5], x2, bias[1])));
    o2 = fmaf(w[6], x0, fmaf(w[7], x1, fmaf(w[8], x2, bias[2])));
}

// Stage prepacked FFN weights global -> smem (no trailing sync; caller's barrier covers).
__device__ __forceinline__ void stage_wff(float4* s_wff, const float4* g) {
    int t = threadIdx.x;
    #pragma unroll
    for (int i = 0; i < 4; ++i) s_wff[t + 256*i] = g[t + 256*i];
}

// pos_enc row s: first 3 sin columns, invf[e] = 10000^(-2e/256) (prep kernel only)
__device__ __forceinline__ void pos3(int s, float& p0, float& p1, float& p2) {
    const float f1 = (float)0.93057204868496882;  // 10000^(-2/256)
    const float f2 = (float)0.86596432336006538;  // 10000^(-4/256)
    float a0 = (float)s;
    p0 = sinf(a0);
    p1 = sinf(a0 * f1);
    p2 = sinf(a0 * f2);
}

// Mq = C_SCALE * Wk^T * Wq ; bq' = C_SCALE * Wk^T * bq  (bk dropped: cancels in softmax)
__device__ void compose_q(const float* in_w, const float* in_b, float* dst) {
    const float* q = in_w;
    const float* k = in_w + 9;
    for (int i = 0; i < 3; ++i) {
        for (int j = 0; j < 3; ++j) {
            float s = 0.f;
            for (int m = 0; m < 3; ++m) s += k[m*3+i] * q[m*3+j];
            dst[i*3+j] = C_SCALE * s;
        }
        float sb = 0.f;
        for (int m = 0; m < 3; ++m) sb += k[m*3+i] * in_b[m];
        dst[9+i] = C_SCALE * sb;
    }
}
// Mvo = Wout * Wv ; bvo = Wout * bv + bout
__device__ void compose_vo(const float* in_w, const float* in_b,
                           const float* ow, const float* ob, float* dst) {
    const float* v  = in_w + 18;
    const float* bv = in_b + 6;
    for (int i = 0; i < 3; ++i) {
        for (int j = 0; j < 3; ++j) {
            float s = 0.f;
            for (int m = 0; m < 3; ++m) s += ow[i*3+m] * v[m*3+j];
            dst[i*3+j] = s;
        }
        float sb = ob[i];
        for (int m = 0; m < 3; ++m) sb += ow[i*3+m] * bv[m];
        dst[9+i] = sb;
    }
}

// Tiny prep kernel: batch-invariant precomputation (pos table, composed mats, packed FFN).
__global__ void prep_kernel(Params P) {
    int t = threadIdx.x;
    {
        float p0, p1, p2;
        pos3(t, p0, p1, p2);
        g_pos[t] = make_float4(p0, p1, p2, 0.f);
    }
    for (int h = t; h < HIDN; h += 256) {
        g_wff_enc[2*h]   = make_float4(P.enc_lin1_w[h*3], P.enc_lin1_w[h*3+1],
                                       P.enc_lin1_w[h*3+2], P.enc_lin1_b[h]);
        g_wff_enc[2*h+1] = make_float4(P.enc_lin2_w[h], P.enc_lin2_w[HIDN+h],
                                       P.enc_lin2_w[2*HIDN+h], 0.f);
        g_wff_dec[2*h]   = make_float4(P.dec_lin1_w[h*3], P.dec_lin1_w[h*3+1],
                                       P.dec_lin1_w[h*3+2], P.dec_lin1_b[h]);
        g_wff_dec[2*h+1] = make_float4(P.dec_lin2_w[h], P.dec_lin2_w[HIDN+h],
                                       P.dec_lin2_w[2*HIDN+h], 0.f);
    }
    if (t == 0) {
        compose_q (P.enc_in_w,    P.enc_in_b,    g_mats);
        compose_vo(P.enc_in_w,    P.enc_in_b,    P.enc_out_w,    P.enc_out_b,    g_mats + 12);
        compose_q (P.dec_a1_in_w, P.dec_a1_in_b, g_mats + 24);
        compose_vo(P.dec_a1_in_w, P.dec_a1_in_b, P.dec_a1_out_w, P.dec_a1_out_b, g_mats + 36);
        compose_q (P.dec_a2_in_w, P.dec_a2_in_b, g_mats + 48);
        compose_vo(P.dec_a2_in_w, P.dec_a2_in_b, P.dec_a2_out_w, P.dec_a2_out_b, g_mats + 60);
    }
}

// One CTA = one batch. Grid caps occupancy at ~7 CTAs/SM.
__global__ void __launch_bounds__(256, 7)
fused_transformer_kernel(Params P) {
    __shared__ __align__(16) float4 s_U[1024];
    __shared__ float s_x2[SIN * 3];
    __shared__ float s_R[SIN * 3];
    __shared__ float s_E[SIN * 3];
    __shared__ float s_red[18];

    float* const sf = (float*)s_U;
    float* const sX = sf;            // 256 floats (enc keys / enc_out keys)
    float* const sY = sf + 256;
    float* const sZ = sf + 512;
    float* const pX = sf + 768;      // 128 floats (pT keys)
    float* const pY = sf + 896;
    float* const pZ = sf + 1024;
    float4* const s_part = s_U + 288;  // attn partials
    float* const qQX = sf + 3200;    // 128 floats: precomputed decoder queries
    float* const qQY = sf + 3328;
    float* const qQZ = sf + 3456;

    const int b    = blockIdx.x;
    const int t    = threadIdx.x;
    const int r128 = t & 127, half2 = t >> 7;
    const int r64  = t & 63,  q4    = t >> 6;
    const float INV768 = 1.0f / 768.0f;
    const float INV384 = 1.0f / 384.0f;

    const float4 pe = g_pos[t];

    // ================= ENCODER =================
    // E1: pX = X + pos_enc -> SoA keys
    {
        const float* xr = P.X + ((size_t)b * SIN + t) * 3;
        sX[t] = xr[0] + pe.x;
        sY[t] = xr[1] + pe.y;
        sZ[t] = xr[2] + pe.z;
    }
    __syncthreads();

    // E2 + LN1 fused: attention -> residual in regs -> LN reduction.
    // Enc FFN weights staged inside the LN (after block_sum2, keys provably dead).
    {
        float x0 = sX[t], x1 = sY[t], x2v = sZ[t];
        float q0, q1, q2;
        proj3(g_mats, g_mats + 9, x0, x1, x2v, q0, q1, q2);   // composed Mq_enc
        u64 q0p = pack2(q0, q0), q1p = pack2(q1, q1), q2p = pack2(q2, q2);
        u64 aX = 0, aY = 0, aZ = 0, aL = 0;
        const double2* X2 = (const double2*)sX;
        const double2* Y2 = (const double2*)sY;
        const double2* Z2 = (const double2*)sZ;
        #pragma unroll 4
        for (int i = 0; i < 64; ++i) {
            double2 dx = X2[i], dy = Y2[i], dz = Z2[i];
            qstep(q0p, q1p, q2p,
                  __double_as_longlong(dx.x), __double_as_longlong(dy.x), __double_as_longlong(dz.x),
                  aX, aY, aZ, aL);
            qstep(q0p, q1p, q2p,
                  __double_as_longlong(dx.y), __double_as_longlong(dy.y), __double_as_longlong(dz.y),
                  aX, aY, aZ, aL);
        }
        float ax, ay, az, l;
        hsum4(aX, aY, aZ, aL, ax, ay, az, l);
        float inv = rcpf(l);
        float r0, r1, r2;
        proj3(g_mats + 12, g_mats + 21, ax*inv, ay*inv, az*inv, r0, r1, r2);  // composed Vo_enc
        r0 += x0; r1 += x1; r2 += x2v;

        float s1 = r0 + r1 + r2;
        float s2 = fmaf(r0, r0, fmaf(r1, r1, r2 * r2));
        block_sum2(s1, s2, s_red);
        stage_wff(s_U, g_wff_enc);
        float mean = s1 * INV768;
        float var  = fmaf(-mean, mean, s2 * INV768);
        float rs = rsqrtf(var + 1e-5f);
        s_x2[t*3+0] = (r0 - mean) * rs * P.enc_ln1_w[t*3+0] + P.enc_ln1_b[t*3+0];
        s_x2[t*3+1] = (r1 - mean) * rs * P.enc_ln1_w[t*3+1] + P.enc_ln1_b[t*3+1];
        s_x2[t*3+2] = (r2 - mean) * rs * P.enc_ln1_w[t*3+2] + P.enc_ln1_b[t*3+2];
    }
    __syncthreads();   // covers s_x2 writes AND weight staging

    // E3: FFN. 2 rows {r128, r128+128} x 256 hidden (half2 split).
    {
        int rowA = r128, rowB = r128 + 128;
        float xA0=s_x2[rowA*3], xA1=s_x2[rowA*3+1], xA2=s_x2[rowA*3+2];
        float xB0=s_x2[rowB*3], xB1=s_x2[rowB*3+1], xB2=s_x2[rowB*3+2];
        float aA0=0.f,aA1=0.f,aA2=0.f, aB0=0.f,aB1=0.f,aB2=0.f;
        int h0 = half2 * 256;
        #pragma unroll 4
        for (int h = h0; h < h0 + 256; ++h) {
            float4 w1 = s_U[2*h];
            float4 w2 = s_U[2*h+1];
            float tA = fmaxf(fmaf(w1.x, xA0, fmaf(w1.y, xA1, fmaf(w1.z, xA2, w1.w))), 0.f);
            float tB = fmaxf(fmaf(w1.x, xB0, fmaf(w1.y, xB1, fmaf(w1.z, xB2, w1.w))), 0.f);
            aA0 = fmaf(tA, w2.x, aA0); aA1 = fmaf(tA, w2.y, aA1); aA2 = fmaf(tA, w2.z, aA2);
            aB0 = fmaf(tB, w2.x, aB0); aB1 = fmaf(tB, w2.y, aB1); aB2 = fmaf(tB, w2.z, aB2);
        }
        float* dst = half2 ? s_R : s_E;
        dst[rowA*3+0]=aA0; dst[rowA*3+1]=aA1; dst[rowA*3+2]=aA2;
        dst[rowB*3+0]=aB0; dst[rowB*3+1]=aB1; dst[rowB*3+2]=aB2;
    }
    __syncthreads();   // FFN partials visible; weights + keys region dead

    // combine + LN2 fused -> enc_out keys (SoA) ; also pT load + q_self precompute.
    {
        float r0 = s_E[t*3+0] + s_R[t*3+0] + P.enc_lin2_b[0] + s_x2[t*3+0];
        float r1 = s_E[t*3+1] + s_R[t*3+1] + P.enc_lin2_b[1] + s_x2[t*3+1];
        float r2 = s_E[t*3+2] + s_R[t*3+2] + P.enc_lin2_b[2] + s_x2[t*3+2];
        float s1 = r0 + r1 + r2;
        float s2 = fmaf(r0, r0, fmaf(r1, r1, r2 * r2));
        block_sum2(s1, s2, s_red);
        float mean = s1 * INV768;
        float var  = fmaf(-mean, mean, s2 * INV768);
        float rs = rsqrtf(var + 1e-5f);
        sX[t] = (r0 - mean) * rs * P.enc_ln2_w[t*3+0] + P.enc_ln2_b[t*3+0];
        sY[t] = (r1 - mean) * rs * P.enc_ln2_w[t*3+1] + P.enc_ln2_b[t*3+1];
        sZ[t] = (r2 - mean) * rs * P.enc_ln2_w[t*3+2] + P.enc_ln2_b[t*3+2];
        if (t < SPR) {
            const float* tr = P.T + ((size_t)b * SPR + t) * 3;
            float x0 = tr[0] + pe.x, x1 = tr[1] + pe.y, x2v = tr[2] + pe.z;
            pX[t] = x0; pY[t] = x1; pZ[t] = x2v;
            float q0, q1, q2;
            proj3(g_mats + 24, g_mats + 33, x0, x1, x2v, q0, q1, q2);  // composed Mq_dec1
            qQX[t] = q0; qQY[t] = q1; qQZ[t] = q2;
        }
    }
    __syncthreads();

    // ================= DECODER =================
    // D2: dec self-attn. Query-pair {r64, r64+64} (q from smem) x 32-key quarter.
    {
        int rowA = r64, rowB = r64 + 64;
        u64 qp0 = pack2(qQX[rowA], qQX[rowB]);
        u64 qp1 = pack2(qQY[rowA], qQY[rowB]);
        u64 qp2 = pack2(qQZ[rowA], qQZ[rowB]);
        u64 aX = 0, aY = 0, aZ = 0, aL = 0;
        int j0 = q4 * 32;
        #pragma unroll 4
        for (int j = j0; j < j0 + 32; ++j)
            qpair_step_m(qp0, qp1, qp2, pX[j], pY[j], pZ[j], j, rowA, rowB, aX, aY, aZ, aL);
        float lA,lB, axA,axB, ayA,ayB, azA,azB;
        unpack2(aL, lA, lB); unpack2(aX, axA, axB);
        unpack2(aY, ayA, ayB); unpack2(aZ, azA, azB);
        s_part[rowA*4 + q4] = make_float4(lA, axA, ayA, azA);
        s_part[rowB*4 + q4] = make_float4(lB, axB, ayB, azB);
    }
    __syncthreads();
    // D2 merge + LN fused -> s_x2 ; cross-query precompute into qQ.
    {
        float r0 = 0.f, r1 = 0.f, r2 = 0.f;
        if (t < SPR) {
            float4 p0 = s_part[t*4], p1 = s_part[t*4+1], p2 = s_part[t*4+2], p3 = s_part[t*4+3];
            float inv = rcpf(p0.x + p1.x + p2.x + p3.x);
            proj3(g_mats + 36, g_mats + 45,                                  // composed Vo_dec1
                  (p0.y+p1.y+p2.y+p3.y)*inv, (p0.z+p1.z+p2.z+p3.z)*inv, (p0.w+p1.w+p2.w+p3.w)*inv,
                  r0, r1, r2);
            r0 += pX[t]; r1 += pY[t]; r2 += pZ[t];
        }
        float s1 = r0 + r1 + r2;
        float s2 = fmaf(r0, r0, fmaf(r1, r1, r2 * r2));
        block_sum2(s1, s2, s_red);
        if (t < SPR) {
            float mean = s1 * INV384;
            float var  = fmaf(-mean, mean, s2 * INV384);
            float rs = rsqrtf(var + 1e-5f);
            float o0 = (r0 - mean) * rs * P.dec_ln1_w[t*3+0] + P.dec_ln1_b[t*3+0];
            float o1 = (r1 - mean) * rs * P.dec_ln1_w[t*3+1] + P.dec_ln1_b[t*3+1];
            float o2 = (r2 - mean) * rs * P.dec_ln1_w[t*3+2] + P.dec_ln1_b[t*3+2];
            s_x2[t*3+0] = o0; s_x2[t*3+1] = o1; s_x2[t*3+2] = o2;
            float q0, q1, q2;
            proj3(g_mats + 48, g_mats + 57, o0, o1, o2, q0, q1, q2);         // composed Mq_dec2
            qQX[t] = q0; qQY[t] = q1; qQZ[t] = q2;
        }
    }
    __syncthreads();

    // D4: cross-attn. Query-pair {r64, r64+64} (q from smem) x 64-key quarter.
    {
        int rowA = r64, rowB = r64 + 64;
        u64 qp0 = pack2(qQX[rowA], qQX[rowB]);
        u64 qp1 = pack2(qQY[rowA], qQY[rowB]);
        u64 qp2 = pack2(qQZ[rowA], qQZ[rowB]);
        u64 aX = 0, aY = 0, aZ = 0, aL = 0;
        int j0 = q4 * 64;
        #pragma unroll 4
        for (int j = j0; j < j0 + 64; ++j)
            qpair_step(qp0, qp1, qp2, sX[j], sY[j], sZ[j], aX, aY, aZ, aL);
        float lA,lB, axA,axB, ayA,ayB, azA,azB;
        unpack2(aL, lA, lB); unpack2(aX, axA, axB);
        unpack2(aY, ayA, ayB); unpack2(aZ, azA, azB);
        s_part[rowA*4 + q4] = make_float4(lA, axA, ayA, azA);
        s_part[rowB*4 + q4] = make_float4(lB, axB, ayB, azB);
    }
    __syncthreads();
    // D4 merge + LN fused -> x3 in s_x2. Dec FFN weights staged after block_sum2.
    {
        float r0 = 0.f, r1 = 0.f, r2 = 0.f;
        if (t < SPR) {
            float4 p0 = s_part[t*4], p1 = s_part[t*4+1], p2 = s_part[t*4+2], p3 = s_part[t*4+3];
            float inv = rcpf(p0.x + p1.x + p2.x + p3.x);
            proj3(g_mats + 60, g_mats + 69,                                  // composed Vo_dec2
                  (p0.y+p1.y+p2.y+p3.y)*inv, (p0.z+p1.z+p2.z+p3.z)*inv, (p0.w+p1.w+p2.w+p3.w)*inv,
                  r0, r1, r2);
            r0 += s_x2[t*3+0]; r1 += s_x2[t*3+1]; r2 += s_x2[t*3+2];
        }
        float s1 = r0 + r1 + r2;
        float s2 = fmaf(r0, r0, fmaf(r1, r1, r2 * r2));
        block_sum2(s1, s2, s_red);
        stage_wff(s_U, g_wff_dec);
        if (t < SPR) {
            float mean = s1 * INV384;
            float var  = fmaf(-mean, mean, s2 * INV384);
            float rs = rsqrtf(var + 1e-5f);
            s_x2[t*3+0] = (r0 - mean) * rs * P.dec_ln1_w[t*3+0] + P.dec_ln1_b[t*3+0];
            s_x2[t*3+1] = (r1 - mean) * rs * P.dec_ln1_w[t*3+1] + P.dec_ln1_b[t*3+1];
            s_x2[t*3+2] = (r2 - mean) * rs * P.dec_ln1_w[t*3+2] + P.dec_ln1_b[t*3+2];
        }
    }
    __syncthreads();   // covers x3 writes AND weight staging

    // D5: dec FFN. 2 rows {r64, r64+64} x 128 hidden (quarter q4).
    {
        int rowA = r64, rowB = r64 + 64;
        float xA0=s_x2[rowA*3], xA1=s_x2[rowA*3+1], xA2=s_x2[rowA*3+2];
        float xB0=s_x2[rowB*3], xB1=s_x2[rowB*3+1], xB2=s_x2[rowB*3+2];
        float aA0=0.f,aA1=0.f,aA2=0.f, aB0=0.f,aB1=0.f,aB2=0.f;
        int h0 = q4 * 128;
        #pragma unroll 4
        for (int h = h0; h < h0 + 128; ++h) {
            float4 w1 = s_U[2*h];
            float4 w2 = s_U[2*h+1];
            float tA = fmaxf(fmaf(w1.x, xA0, fmaf(w1.y, xA1, fmaf(w1.z, xA2, w1.w))), 0.f);
            float tB = fmaxf(fmaf(w1.x, xB0, fmaf(w1.y, xB1, fmaf(w1.z, xB2, w1.w))), 0.f);
            aA0 = fmaf(tA, w2.x, aA0); aA1 = fmaf(tA, w2.y, aA1); aA2 = fmaf(tA, w2.z, aA2);
            aB0 = fmaf(tB, w2.x, aB0); aB1 = fmaf(tB, w2.y, aB1); aB2 = fmaf(tB, w2.z, aB2);
        }
        float* dst = (q4 < 2) ? s_R : s_E;
        int off = (q4 & 1) * 384;
        dst[off + rowA*3+0]=aA0; dst[off + rowA*3+1]=aA1; dst[off + rowA*3+2]=aA2;
        dst[off + rowB*3+0]=aB0; dst[off + rowB*3+1]=aB1; dst[off + rowB*3+2]=aB2;
    }
    __syncthreads();

    // final combine + LN3 fused -> global output (no trailing barrier).
    {
        float r0 = 0.f, r1 = 0.f, r2 = 0.f;
        if (t < SPR) {
            r0 = s_R[t*3+0] + s_R[384+t*3+0] + s_E[t*3+0] + s_E[384+t*3+0]
               + P.dec_lin2_b[0] + s_x2[t*3+0];
            r1 = s_R[t*3+1] + s_R[384+t*3+1] + s_E[t*3+1] + s_E[384+t*3+1]
               + P.dec_lin2_b[1] + s_x2[t*3+1];
            r2 = s_R[t*3+2] + s_R[384+t*3+2] + s_E[t*3+2] + s_E[384+t*3+2]
               + P.dec_lin2_b[2] + s_x2[t*3+2];
        }
        float s1 = r0 + r1 + r2;
        float s2 = fmaf(r0, r0, fmaf(r1, r1, r2 * r2));
        block_sum2(s1, s2, s_red);
        if (t < SPR) {
            float mean = s1 * INV384;
            float var  = fmaf(-mean, mean, s2 * INV384);
            float rs = rsqrtf(var + 1e-5f);
            float* o = P.out + ((size_t)b * SPR + t) * 3;
            o[0] = (r0 - mean) * rs * P.dec_ln3_w[t*3+0] + P.dec_ln3_b[t*3+0];
            o[1] = (r1 - mean) * rs * P.dec_ln3_w[t*3+1] + P.dec_ln3_b[t*3+1];
            o[2] = (r2 - mean) * rs * P.dec_ln3_w[t*3+2] + P.dec_ln3_b[t*3+2];
        }
    }
}

extern "C" void kernel_launch(void* const* d_in, const int* in_sizes, int n_in,
                              void* d_out, int out_size) {
    (void)in_sizes; (void)n_in; (void)out_size;
    Params P;
    P.X            = (const float*)d_in[0];
    P.T            = (const float*)d_in[1];
    P.enc_in_w     = (const float*)d_in[2];
    P.enc_in_b     = (const float*)d_in[3];
    P.enc_out_w    = (const float*)d_in[4];
    P.enc_out_b    = (const float*)d_in[5];
    P.enc_ln1_w    = (const float*)d_in[6];
    P.enc_ln1_b    = (const float*)d_in[7];
    P.enc_lin1_w   = (const float*)d_in[8];
    P.enc_lin1_b   = (const float*)d_in[9];
    P.enc_lin2_w   = (const float*)d_in[10];
    P.enc_lin2_b   = (const float*)d_in[11];
    P.enc_ln2_w    = (const float*)d_in[12];
    P.enc_ln2_b    = (const float*)d_in[13];
    P.dec_a1_in_w  = (const float*)d_in[14];
    P.dec_a1_in_b  = (const float*)d_in[15];
    P.dec_a1_out_w = (const float*)d_in[16];
    P.dec_a1_out_b = (const float*)d_in[17];
    P.dec_ln1_w    = (const float*)d_in[18];
    P.dec_ln1_b    = (const float*)d_in[19];
    P.dec_a2_in_w  = (const float*)d_in[20];
    P.dec_a2_in_b  = (const float*)d_in[21];
    P.dec_a2_out_w = (const float*)d_in[22];
    P.dec_a2_out_b = (const float*)d_in[23];
    P.dec_lin1_w   = (const float*)d_in[24];
    P.dec_lin1_b   = (const float*)d_in[25];
    P.dec_lin2_w   = (const float*)d_in[26];
    P.dec_lin2_b   = (const float*)d_in[27];
    P.dec_ln3_w    = (const float*)d_in[28];
    P.dec_ln3_b    = (const float*)d_in[29];
    P.out          = (float*)d_out;

    prep_kernel<<<1, 256>>>(P);
    fused_transformer_kernel<<<NB, 256>>>(P);
}

// round 16
// speedup vs baseline: 1.0698x; 1.0698x over previous
#include <cuda_runtime.h>
#include <math.h>

#define NB    1024
#define SIN   256
#define SPR   128
#define HIDN  512

// 1/sqrt(3) * log2(e): fold scores into exp2 domain
#define C_SCALE 0.83294064f
// log2(e): additive causal "mask" of +1.0 in exp2 domain
#define L2E 1.4426950408889634f

typedef unsigned long long u64;

struct Params {
    const float* X;           const float* T;
    const float* enc_in_w;    const float* enc_in_b;
    const float* enc_out_w;   const float* enc_out_b;
    const float* enc_ln1_w;   const float* enc_ln1_b;
    const float* enc_lin1_w;  const float* enc_lin1_b;
    const float* enc_lin2_w;  const float* enc_lin2_b;
    const float* enc_ln2_w;   const float* enc_ln2_b;
    const float* dec_a1_in_w; const float* dec_a1_in_b;
    const float* dec_a1_out_w;const float* dec_a1_out_b;
    const float* dec_ln1_w;   const float* dec_ln1_b;
    const float* dec_a2_in_w; const float* dec_a2_in_b;
    const float* dec_a2_out_w;const float* dec_a2_out_b;
    const float* dec_lin1_w;  const float* dec_lin1_b;
    const float* dec_lin2_w;  const float* dec_lin2_b;
    const float* dec_ln3_w;   const float* dec_ln3_b;
    float* out;
};

__device__ __forceinline__ float ex2f(float x) {
    float y; asm("ex2.approx.ftz.f32 %0, %1;" : "=f"(y) : "f"(x)); return y;
}
__device__ __forceinline__ float rcpf(float x) {
    float y; asm("rcp.approx.ftz.f32 %0, %1;" : "=f"(y) : "f"(x)); return y;
}

// ---- packed f32x2 ops (Blackwell) ----
__device__ __forceinline__ u64 fma2(u64 a, u64 b, u64 c) {
    u64 d; asm("fma.rn.f32x2 %0, %1, %2, %3;" : "=l"(d) : "l"(a), "l"(b), "l"(c)); return d;
}
__device__ __forceinline__ u64 mul2(u64 a, u64 b) {
    u64 d; asm("mul.rn.f32x2 %0, %1, %2;" : "=l"(d) : "l"(a), "l"(b)); return d;
}
__device__ __forceinline__ u64 add2(u64 a, u64 b) {
    u64 d; asm("add.rn.f32x2 %0, %1, %2;" : "=l"(d) : "l"(a), "l"(b)); return d;
}
__device__ __forceinline__ u64 pack2(float lo, float hi) {
    u64 d; asm("mov.b64 %0, {%1, %2};" : "=l"(d) : "f"(lo), "f"(hi)); return d;
}
__device__ __forceinline__ void unpack2(u64 d, float& a, float& b) {
    asm("mov.b64 {%0, %1}, %2;" : "=f"(a), "=f"(b) : "l"(d));
}
__device__ __forceinline__ float hadd2(u64 d) {
    float a, b; unpack2(d, a, b); return a + b;
}

// Key-pair attention step: lanes = 2 keys vs 1 broadcast query.
__device__ __forceinline__ void qstep(u64 q0p, u64 q1p, u64 q2p,
                                      u64 xp, u64 yp, u64 zp,
                                      u64& aX, u64& aY, u64& aZ, u64& aL) {
    u64 d = fma2(q2p, zp, fma2(q1p, yp, mul2(q0p, xp)));
    float s0, s1; unpack2(d, s0, s1);
    u64 pp = pack2(ex2f(s0), ex2f(s1));
    aX = fma2(pp, xp, aX);
    aY = fma2(pp, yp, aY);
    aZ = fma2(pp, zp, aZ);
    aL = add2(aL, pp);
}
__device__ __forceinline__ void hsum4(u64 aX, u64 aY, u64 aZ, u64 aL,
                                      float& x, float& y, float& z, float& l) {
    x = hadd2(aX); y = hadd2(aY); z = hadd2(aZ); l = hadd2(aL);
}

// Query-pair step: lanes = (queryA, queryB), key broadcast in both lanes.
__device__ __forceinline__ void qpair_step(u64 qp0, u64 qp1, u64 qp2,
                                           float kx, float ky, float kz,
                                           u64& aX, u64& aY, u64& aZ, u64& aL) {
    u64 kxp = pack2(kx, kx), kyp = pack2(ky, ky), kzp = pack2(kz, kz);
    u64 d = fma2(qp2, kzp, fma2(qp1, kyp, mul2(qp0, kxp)));
    float sA, sB; unpack2(d, sA, sB);
    u64 pp = pack2(ex2f(sA), ex2f(sB));
    aX = fma2(pp, kxp, aX);
    aY = fma2(pp, kyp, aY);
    aZ = fma2(pp, kzp, aZ);
    aL = add2(aL, pp);
}
// Masked: reference ADDS tril(ones) -> +log2(e) in exp2 domain, per lane.
__device__ __forceinline__ void qpair_step_m(u64 qp0, u64 qp1, u64 qp2,
                                             float kx, float ky, float kz,
                                             int j, int rowA, int rowB,
                                             u64& aX, u64& aY, u64& aZ, u64& aL) {
    u64 kxp = pack2(kx, kx), kyp = pack2(ky, ky), kzp = pack2(kz, kz);
    u64 d = fma2(qp2, kzp, fma2(qp1, kyp, mul2(qp0, kxp)));
    float sA, sB; unpack2(d, sA, sB);
    sA += (j <= rowA) ? L2E : 0.f;
    sB += (j <= rowB) ? L2E : 0.f;
    u64 pp = pack2(ex2f(sA), ex2f(sB));
    aX = fma2(pp, kxp, aX);
    aY = fma2(pp, kyp, aY);
    aZ = fma2(pp, kzp, aZ);
    aL = add2(aL, pp);
}

// Fused two-value block reduction (2 barriers). (Proven R12 form.)
__device__ __forceinline__ void block_sum2(float& a, float& b, float* red) {
    #pragma unroll
    for (int o = 16; o; o >>= 1) {
        a += __shfl_xor_sync(0xffffffffu, a, o);
        b += __shfl_xor_sync(0xffffffffu, b, o);
    }
    int w = threadIdx.x >> 5;
    if ((threadIdx.x & 31) == 0) { red[w] = a; red[8 + w] = b; }
    __syncthreads();
    if (threadIdx.x < 16) {
        float x = red[threadIdx.x];
        x += __shfl_xor_sync(0x0000ffffu, x, 4);
        x += __shfl_xor_sync(0x0000ffffu, x, 2);
        x += __shfl_xor_sync(0x0000ffffu, x, 1);
        if ((threadIdx.x & 7) == 0) red[16 + (threadIdx.x >> 3)] = x;
    }
    __syncthreads();
    a = red[16]; b = red[17];
}

__device__ __forceinline__ void proj3(const float* w, const float* bias,
                                      float x0, float x1, float x2,
                                      float& o0, float& o1, float& o2) {
    o0 = fmaf(w[0], x0, fmaf(w[1], x1, fmaf(w[2], x2, bias[0])));
    o1 = fmaf(w[3], x0, fmaf(w[4], x1, fmaf(w[5], x2, bias[1])));
    o2 = fmaf(w[6], x0, fmaf(w[7], x1, fmaf(w[8], x2, bias[2])));
}

// Weight staging WITHOUT trailing sync — caller's next barrier covers visibility.
__device__ __forceinline__ void load_wff_nosync(float4* s_wff, const float* w1,
                                                const float* b1, const float* w2) {
    for (int h = threadIdx.x; h < HIDN; h += 256) {
        s_wff[2*h]   = make_float4(w1[h*3], w1[h*3+1], w1[h*3+2], b1[h]);
        s_wff[2*h+1] = make_float4(w2[h], w2[HIDN + h], w2[2*HIDN + h], 0.f);
    }
}

// pos_enc row s: first 3 sin columns, invf[e] = 10000^(-2e/256)
__device__ __forceinline__ void pos3(int s, float& p0, float& p1, float& p2) {
    const float f1 = (float)0.93057204868496882;  // 10000^(-2/256)
    const float f2 = (float)0.86596432336006538;  // 10000^(-4/256)
    float a0 = (float)s;
    p0 = sinf(a0);
    p1 = sinf(a0 * f1);
    p2 = sinf(a0 * f2);
}

// Per-CTA composed-matrix setup: threads 0..71 each compute one element.
// Layout (12 floats each): [0)MqE [12)VoE [24)MqD1 [36)VoD1 [48)MqD2 [60)VoD2
//   Mq  = C_SCALE * Wk^T * Wq ; bq' = C_SCALE * Wk^T * bq (bk cancels in softmax)
//   Vo  = Wout * Wv ;           bvo = Wout * bv + bout
__device__ __forceinline__ void compose_mats(float* s_mats, const Params& P) {
    int t = threadIdx.x;
    if (t >= 72) return;
    int blk = t / 12;        // 0..5
    int idx = t - blk * 12;  // 0..11
    const float *in_w, *in_b, *ow, *ob;
    int pair = blk >> 1;
    if (pair == 0)      { in_w = P.enc_in_w;    in_b = P.enc_in_b;    ow = P.enc_out_w;    ob = P.enc_out_b; }
    else if (pair == 1) { in_w = P.dec_a1_in_w; in_b = P.dec_a1_in_b; ow = P.dec_a1_out_w; ob = P.dec_a1_out_b; }
    else                { in_w = P.dec_a2_in_w; in_b = P.dec_a2_in_b; ow = P.dec_a2_out_w; ob = P.dec_a2_out_b; }
    float r;
    if ((blk & 1) == 0) {           // Mq block
        const float* q = in_w;
        const float* k = in_w + 9;
        if (idx < 9) {
            int i = idx / 3, j = idx - i * 3;
            r = k[0*3+i]*q[0*3+j] + k[1*3+i]*q[1*3+j] + k[2*3+i]*q[2*3+j];
        } else {
            int i = idx - 9;
            r = k[0*3+i]*in_b[0] + k[1*3+i]*in_b[1] + k[2*3+i]*in_b[2];
        }
        r *= C_SCALE;
    } else {                         // Vo block
        const float* v  = in_w + 18;
        const float* bv = in_b + 6;
        if (idx < 9) {
            int i = idx / 3, j = idx - i * 3;
            r = ow[i*3+0]*v[0*3+j] + ow[i*3+1]*v[1*3+j] + ow[i*3+2]*v[2*3+j];
        } else {
            int i = idx - 9;
            r = ob[i] + ow[i*3+0]*bv[0] + ow[i*3+1]*bv[1] + ow[i*3+2]*bv[2];
        }
    }
    s_mats[blk * 12 + idx] = r;
}

// One CTA = one batch. Grid caps occupancy at ~7 CTAs/SM.
__global__ void __launch_bounds__(256, 7)
fused_transformer_kernel(Params P) {
    __shared__ __align__(16) float4 s_U[1024];
    __shared__ float s_x2[SIN * 3];
    __shared__ float s_R[SIN * 3];
    __shared__ float s_E[SIN * 3];
    __shared__ float s_red[18];
    __shared__ float s_mats[72];

    float* const sf = (float*)s_U;
    float* const sX = sf;            // 256 floats (enc keys / enc_out keys)
    float* const sY = sf + 256;
    float* const sZ = sf + 512;
    float* const pX = sf + 768;      // 128 floats (pT keys)
    float* const pY = sf + 896;
    float* const pZ = sf + 1024;
    float4* const s_part = s_U + 288;  // attn partials
    float* const qQX = sf + 3200;    // 128 floats: precomputed decoder queries
    float* const qQY = sf + 3328;
    float* const qQZ = sf + 3456;

    const int b    = blockIdx.x;
    const int t    = threadIdx.x;
    const int r128 = t & 127, half2 = t >> 7;
    const int r64  = t & 63,  q4    = t >> 6;
    const float INV768 = 1.0f / 768.0f;
    const float INV384 = 1.0f / 384.0f;

    float pe0, pe1, pe2;
    pos3(t, pe0, pe1, pe2);

    // ================= ENCODER =================
    // E1: pX = X + pos_enc -> SoA keys ; threads 0..71 compose attention mats.
    {
        const float* xr = P.X + ((size_t)b * SIN + t) * 3;
        sX[t] = xr[0] + pe0;
        sY[t] = xr[1] + pe1;
        sZ[t] = xr[2] + pe2;
    }
    compose_mats(s_mats, P);
    __syncthreads();

    // E2 + LN1 fused: attention -> residual r in regs -> LN reduction.
    // Enc FFN weights staged inside the LN (after block_sum2, keys provably dead).
    {
        float x0 = sX[t], x1 = sY[t], x2v = sZ[t];
        float q0, q1, q2;
        proj3(s_mats, s_mats + 9, x0, x1, x2v, q0, q1, q2);   // composed Mq_enc
        u64 q0p = pack2(q0, q0), q1p = pack2(q1, q1), q2p = pack2(q2, q2);
        u64 aX = 0, aY = 0, aZ = 0, aL = 0;
        const double2* X2 = (const double2*)sX;
        const double2* Y2 = (const double2*)sY;
        const double2* Z2 = (const double2*)sZ;
        #pragma unroll 4
        for (int i = 0; i < 64; ++i) {
            double2 dx = X2[i], dy = Y2[i], dz = Z2[i];
            qstep(q0p, q1p, q2p,
                  __double_as_longlong(dx.x), __double_as_longlong(dy.x), __double_as_longlong(dz.x),
                  aX, aY, aZ, aL);
            qstep(q0p, q1p, q2p,
                  __double_as_longlong(dx.y), __double_as_longlong(dy.y), __double_as_longlong(dz.y),
                  aX, aY, aZ, aL);
        }
        float ax, ay, az, l;
        hsum4(aX, aY, aZ, aL, ax, ay, az, l);
        float inv = rcpf(l);
        float r0, r1, r2;
        proj3(s_mats + 12, s_mats + 21, ax*inv, ay*inv, az*inv, r0, r1, r2);  // composed Vo_enc
        r0 += x0; r1 += x1; r2 += x2v;

        float s1 = r0 + r1 + r2;
        float s2 = fmaf(r0, r0, fmaf(r1, r1, r2 * r2));
        block_sum2(s1, s2, s_red);
        load_wff_nosync(s_U, P.enc_lin1_w, P.enc_lin1_b, P.enc_lin2_w);
        float mean = s1 * INV768;
        float var  = fmaf(-mean, mean, s2 * INV768);
        float rs = rsqrtf(var + 1e-5f);
        s_x2[t*3+0] = (r0 - mean) * rs * P.enc_ln1_w[t*3+0] + P.enc_ln1_b[t*3+0];
        s_x2[t*3+1] = (r1 - mean) * rs * P.enc_ln1_w[t*3+1] + P.enc_ln1_b[t*3+1];
        s_x2[t*3+2] = (r2 - mean) * rs * P.enc_ln1_w[t*3+2] + P.enc_ln1_b[t*3+2];
    }
    __syncthreads();   // covers s_x2 writes AND weight staging

    // E3: FFN. 2 rows {r128, r128+128} x 256 hidden (half2 split).
    {
        int rowA = r128, rowB = r128 + 128;
        float xA0=s_x2[rowA*3], xA1=s_x2[rowA*3+1], xA2=s_x2[rowA*3+2];
        float xB0=s_x2[rowB*3], xB1=s_x2[rowB*3+1], xB2=s_x2[rowB*3+2];
        float aA0=0.f,aA1=0.f,aA2=0.f, aB0=0.f,aB1=0.f,aB2=0.f;
        int h0 = half2 * 256;
        #pragma unroll 4
        for (int h = h0; h < h0 + 256; ++h) {
            float4 w1 = s_U[2*h];
            float4 w2 = s_U[2*h+1];
            float tA = fmaxf(fmaf(w1.x, xA0, fmaf(w1.y, xA1, fmaf(w1.z, xA2, w1.w))), 0.f);
            float tB = fmaxf(fmaf(w1.x, xB0, fmaf(w1.y, xB1, fmaf(w1.z, xB2, w1.w))), 0.f);
            aA0 = fmaf(tA, w2.x, aA0); aA1 = fmaf(tA, w2.y, aA1); aA2 = fmaf(tA, w2.z, aA2);
            aB0 = fmaf(tB, w2.x, aB0); aB1 = fmaf(tB, w2.y, aB1); aB2 = fmaf(tB, w2.z, aB2);
        }
        float* dst = half2 ? s_R : s_E;
        dst[rowA*3+0]=aA0; dst[rowA*3+1]=aA1; dst[rowA*3+2]=aA2;
        dst[rowB*3+0]=aB0; dst[rowB*3+1]=aB1; dst[rowB*3+2]=aB2;
    }
    __syncthreads();   // FFN partials visible; weights + keys region dead

    // combine + LN2 fused -> enc_out keys (SoA) ; also pT load + q_self precompute.
    {
        float r0 = s_E[t*3+0] + s_R[t*3+0] + P.enc_lin2_b[0] + s_x2[t*3+0];
        float r1 = s_E[t*3+1] + s_R[t*3+1] + P.enc_lin2_b[1] + s_x2[t*3+1];
        float r2 = s_E[t*3+2] + s_R[t*3+2] + P.enc_lin2_b[2] + s_x2[t*3+2];
        float s1 = r0 + r1 + r2;
        float s2 = fmaf(r0, r0, fmaf(r1, r1, r2 * r2));
        block_sum2(s1, s2, s_red);
        float mean = s1 * INV768;
        float var  = fmaf(-mean, mean, s2 * INV768);
        float rs = rsqrtf(var + 1e-5f);
        sX[t] = (r0 - mean) * rs * P.enc_ln2_w[t*3+0] + P.enc_ln2_b[t*3+0];
        sY[t] = (r1 - mean) * rs * P.enc_ln2_w[t*3+1] + P.enc_ln2_b[t*3+1];
        sZ[t] = (r2 - mean) * rs * P.enc_ln2_w[t*3+2] + P.enc_ln2_b[t*3+2];
        if (t < SPR) {
            const float* tr = P.T + ((size_t)b * SPR + t) * 3;
            float x0 = tr[0] + pe0, x1 = tr[1] + pe1, x2v = tr[2] + pe2;
            pX[t] = x0; pY[t] = x1; pZ[t] = x2v;
            float q0, q1, q2;
            proj3(s_mats + 24, s_mats + 33, x0, x1, x2v, q0, q1, q2);  // composed Mq_dec1
            qQX[t] = q0; qQY[t] = q1; qQZ[t] = q2;
        }
    }
    __syncthreads();

    // ================= DECODER =================
    // D2: dec self-attn. Query-pair {r64, r64+64} (q from smem) x 32-key quarter.
    {
        int rowA = r64, rowB = r64 + 64;
        u64 qp0 = pack2(qQX[rowA], qQX[rowB]);
        u64 qp1 = pack2(qQY[rowA], qQY[rowB]);
        u64 qp2 = pack2(qQZ[rowA], qQZ[rowB]);
        u64 aX = 0, aY = 0, aZ = 0, aL = 0;
        int j0 = q4 * 32;
        #pragma unroll 4
        for (int j = j0; j < j0 + 32; ++j)
            qpair_step_m(qp0, qp1, qp2, pX[j], pY[j], pZ[j], j, rowA, rowB, aX, aY, aZ, aL);
        float lA,lB, axA,axB, ayA,ayB, azA,azB;
        unpack2(aL, lA, lB); unpack2(aX, axA, axB);
        unpack2(aY, ayA, ayB); unpack2(aZ, azA, azB);
        s_part[rowA*4 + q4] = make_float4(lA, axA, ayA, azA);
        s_part[rowB*4 + q4] = make_float4(lB, axB, ayB, azB);
    }
    __syncthreads();
    // D2 merge + LN fused -> s_x2 ; cross-query precompute into qQ.
    {
        float r0 = 0.f, r1 = 0.f, r2 = 0.f;
        if (t < SPR) {
            float4 p0 = s_part[t*4], p1 = s_part[t*4+1], p2 = s_part[t*4+2], p3 = s_part[t*4+3];
            float inv = rcpf(p0.x + p1.x + p2.x + p3.x);
            proj3(s_mats + 36, s_mats + 45,                                  // composed Vo_dec1
                  (p0.y+p1.y+p2.y+p3.y)*inv, (p0.z+p1.z+p2.z+p3.z)*inv, (p0.w+p1.w+p2.w+p3.w)*inv,
                  r0, r1, r2);
            r0 += pX[t]; r1 += pY[t]; r2 += pZ[t];
        }
        float s1 = r0 + r1 + r2;
        float s2 = fmaf(r0, r0, fmaf(r1, r1, r2 * r2));
        block_sum2(s1, s2, s_red);
        if (t < SPR) {
            float mean = s1 * INV384;
            float var  = fmaf(-mean, mean, s2 * INV384);
            float rs = rsqrtf(var + 1e-5f);
            float o0 = (r0 - mean) * rs * P.dec_ln1_w[t*3+0] + P.dec_ln1_b[t*3+0];
            float o1 = (r1 - mean) * rs * P.dec_ln1_w[t*3+1] + P.dec_ln1_b[t*3+1];
            float o2 = (r2 - mean) * rs * P.dec_ln1_w[t*3+2] + P.dec_ln1_b[t*3+2];
            s_x2[t*3+0] = o0; s_x2[t*3+1] = o1; s_x2[t*3+2] = o2;
            float q0, q1, q2;
            proj3(s_mats + 48, s_mats + 57, o0, o1, o2, q0, q1, q2);         // composed Mq_dec2
            qQX[t] = q0; qQY[t] = q1; qQZ[t] = q2;
        }
    }
    __syncthreads();

    // D4: cross-attn. Query-pair {r64, r64+64} (q from smem) x 64-key quarter.
    {
        int rowA = r64, rowB = r64 + 64;
        u64 qp0 = pack2(qQX[rowA], qQX[rowB]);
        u64 qp1 = pack2(qQY[rowA], qQY[rowB]);
        u64 qp2 = pack2(qQZ[rowA], qQZ[rowB]);
        u64 aX = 0, aY = 0, aZ = 0, aL = 0;
        int j0 = q4 * 64;
        #pragma unroll 4
        for (int j = j0; j < j0 + 64; ++j)
            qpair_step(qp0, qp1, qp2, sX[j], sY[j], sZ[j], aX, aY, aZ, aL);
        float lA,lB, axA,axB, ayA,ayB, azA,azB;
        unpack2(aL, lA, lB); unpack2(aX, axA, axB);
        unpack2(aY, ayA, ayB); unpack2(aZ, azA, azB);
        s_part[rowA*4 + q4] = make_float4(lA, axA, ayA, azA);
        s_part[rowB*4 + q4] = make_float4(lB, axB, ayB, azB);
    }
    __syncthreads();
    // D4 merge + LN fused -> x3 in s_x2. Dec FFN weights staged after block_sum2.
    {
        float r0 = 0.f, r1 = 0.f, r2 = 0.f;
        if (t < SPR) {
            float4 p0 = s_part[t*4], p1 = s_part[t*4+1], p2 = s_part[t*4+2], p3 = s_part[t*4+3];
            float inv = rcpf(p0.x + p1.x + p2.x + p3.x);
            proj3(s_mats + 60, s_mats + 69,                                  // composed Vo_dec2
                  (p0.y+p1.y+p2.y+p3.y)*inv, (p0.z+p1.z+p2.z+p3.z)*inv, (p0.w+p1.w+p2.w+p3.w)*inv,
                  r0, r1, r2);
            r0 += s_x2[t*3+0]; r1 += s_x2[t*3+1]; r2 += s_x2[t*3+2];
        }
        float s1 = r0 + r1 + r2;
        float s2 = fmaf(r0, r0, fmaf(r1, r1, r2 * r2));
        block_sum2(s1, s2, s_red);
        load_wff_nosync(s_U, P.dec_lin1_w, P.dec_lin1_b, P.dec_lin2_w);
        if (t < SPR) {
            float mean = s1 * INV384;
            float var  = fmaf(-mean, mean, s2 * INV384);
            float rs = rsqrtf(var + 1e-5f);
            s_x2[t*3+0] = (r0 - mean) * rs * P.dec_ln1_w[t*3+0] + P.dec_ln1_b[t*3+0];
            s_x2[t*3+1] = (r1 - mean) * rs * P.dec_ln1_w[t*3+1] + P.dec_ln1_b[t*3+1];
            s_x2[t*3+2] = (r2 - mean) * rs * P.dec_ln1_w[t*3+2] + P.dec_ln1_b[t*3+2];
        }
    }
    __syncthreads();   // covers x3 writes AND weight staging

    // D5: dec FFN. 2 rows {r64, r64+64} x 128 hidden (quarter q4).
    {
        int rowA = r64, rowB = r64 + 64;
        float xA0=s_x2[rowA*3], xA1=s_x2[rowA*3+1], xA2=s_x2[rowA*3+2];
        float xB0=s_x2[rowB*3], xB1=s_x2[rowB*3+1], xB2=s_x2[rowB*3+2];
        float aA0=0.f,aA1=0.f,aA2=0.f, aB0=0.f,aB1=0.f,aB2=0.f;
        int h0 = q4 * 128;
        #pragma unroll 4
        for (int h = h0; h < h0 + 128; ++h) {
            float4 w1 = s_U[2*h];
            float4 w2 = s_U[2*h+1];
            float tA = fmaxf(fmaf(w1.x, xA0, fmaf(w1.y, xA1, fmaf(w1.z, xA2, w1.w))), 0.f);
            float tB = fmaxf(fmaf(w1.x, xB0, fmaf(w1.y, xB1, fmaf(w1.z, xB2, w1.w))), 0.f);
            aA0 = fmaf(tA, w2.x, aA0); aA1 = fmaf(tA, w2.y, aA1); aA2 = fmaf(tA, w2.z, aA2);
            aB0 = fmaf(tB, w2.x, aB0); aB1 = fmaf(tB, w2.y, aB1); aB2 = fmaf(tB, w2.z, aB2);
        }
        float* dst = (q4 < 2) ? s_R : s_E;
        int off = (q4 & 1) * 384;
        dst[off + rowA*3+0]=aA0; dst[off + rowA*3+1]=aA1; dst[off + rowA*3+2]=aA2;
        dst[off + rowB*3+0]=aB0; dst[off + rowB*3+1]=aB1; dst[off + rowB*3+2]=aB2;
    }
    __syncthreads();

    // final combine + LN3 fused -> global output (no trailing barrier).
    {
        float r0 = 0.f, r1 = 0.f, r2 = 0.f;
        if (t < SPR) {
            r0 = s_R[t*3+0] + s_R[384+t*3+0] + s_E[t*3+0] + s_E[384+t*3+0]
               + P.dec_lin2_b[0] + s_x2[t*3+0];
            r1 = s_R[t*3+1] + s_R[384+t*3+1] + s_E[t*3+1] + s_E[384+t*3+1]
               + P.dec_lin2_b[1] + s_x2[t*3+1];
            r2 = s_R[t*3+2] + s_R[384+t*3+2] + s_E[t*3+2] + s_E[384+t*3+2]
               + P.dec_lin2_b[2] + s_x2[t*3+2];
        }
        float s1 = r0 + r1 + r2;
        float s2 = fmaf(r0, r0, fmaf(r1, r1, r2 * r2));
        block_sum2(s1, s2, s_red);
        if (t < SPR) {
            float mean = s1 * INV384;
            float var  = fmaf(-mean, mean, s2 * INV384);
            float rs = rsqrtf(var + 1e-5f);
            float* o = P.out + ((size_t)b * SPR + t) * 3;
            o[0] = (r0 - mean) * rs * P.dec_ln3_w[t*3+0] + P.dec_ln3_b[t*3+0];
            o[1] = (r1 - mean) * rs * P.dec_ln3_w[t*3+1] + P.dec_ln3_b[t*3+1];
            o[2] = (r2 - mean) * rs * P.dec_ln3_w[t*3+2] + P.dec_ln3_b[t*3+2];
        }
    }
}

extern "C" void kernel_launch(void* const* d_in, const int* in_sizes, int n_in,
                              void* d_out, int out_size) {
    (void)in_sizes; (void)n_in; (void)out_size;
    Params P;
    P.X            = (const float*)d_in[0];
    P.T            = (const float*)d_in[1];
    P.enc_in_w     = (const float*)d_in[2];
    P.enc_in_b     = (const float*)d_in[3];
    P.enc_out_w    = (const float*)d_in[4];
    P.enc_out_b    = (const float*)d_in[5];
    P.enc_ln1_w    = (const float*)d_in[6];
    P.enc_ln1_b    = (const float*)d_in[7];
    P.enc_lin1_w   = (const float*)d_in[8];
    P.enc_lin1_b   = (const float*)d_in[9];
    P.enc_lin2_w   = (const float*)d_in[10];
    P.enc_lin2_b   = (const float*)d_in[11];
    P.enc_ln2_w    = (const float*)d_in[12];
    P.enc_ln2_b    = (const float*)d_in[13];
    P.dec_a1_in_w  = (const float*)d_in[14];
    P.dec_a1_in_b  = (const float*)d_in[15];
    P.dec_a1_out_w = (const float*)d_in[16];
    P.dec_a1_out_b = (const float*)d_in[17];
    P.dec_ln1_w    = (const float*)d_in[18];
    P.dec_ln1_b    = (const float*)d_in[19];
    P.dec_a2_in_w  = (const float*)d_in[20];
    P.dec_a2_in_b  = (const float*)d_in[21];
    P.dec_a2_out_w = (const float*)d_in[22];
    P.dec_a2_out_b = (const float*)d_in[23];
    P.dec_lin1_w   = (const float*)d_in[24];
    P.dec_lin1_b   = (const float*)d_in[25];
    P.dec_lin2_w   = (const float*)d_in[26];
    P.dec_lin2_b   = (const float*)d_in[27];
    P.dec_ln3_w    = (const float*)d_in[28];
    P.dec_ln3_b    = (const float*)d_in[29];
    P.out          = (float*)d_out;

    fused_transformer_kernel<<<NB, 256>>>(P);
}